// round 4
// baseline (speedup 1.0000x reference)
#include <cuda_runtime.h>
#include <cstdint>

// SoftNormalShader: gather vertex normals + barycentric interp + softmax RGB blend.
// N=4,H=512,W=512,K=8 ; V=50000, F=100000.
// Inputs (JAX x64 disabled => int arrays are int32):
//   0: verts_normals (V,3) f32   1: bary (P,8,3) f32   2: dists (P,8) f32
//   3: zbuf (P,8) f32            4: faces (F,3) i32    5: pix_to_face (P,8) i32
// Output: (N,H,W,4) float32
//
// Strategy: L1-wavefront-bound on scalar gathers -> pack gather tables into
// float4/int4 device scratch (1 wide load instead of 3 scalars), lazy bary
// with b2 reconstructed, bitmask-compacted weight loop (GAMMA=1e-4 underflow
// means ~1 of 8 samples carries nonzero weight).

#define KSAMP 8
#define SIGMA_INV  1e4f
#define GAMMA_INV  1e4f
#define ZFAR_F     100.0f
#define INV_RANGE  (1.0f / 99.0f)
#define EPS_F      1e-10f

#define MAXV 65536
#define MAXF 131072

__device__ float4 g_vn4[MAXV];     // packed vertex normals (x,y,z,0)
__device__ int4   g_faces4[MAXF];  // packed face vertex indices (v0,v1,v2,0)

__global__ void pack_vn_kernel(const float* __restrict__ vn, int V)
{
    int v = blockIdx.x * blockDim.x + threadIdx.x;
    if (v < V && v < MAXV) {
        const float* r = vn + (long long)v * 3;
        g_vn4[v] = make_float4(__ldg(r + 0), __ldg(r + 1), __ldg(r + 2), 0.0f);
    }
}

__global__ void pack_faces_kernel(const int* __restrict__ faces, int F)
{
    int f = blockIdx.x * blockDim.x + threadIdx.x;
    if (f < F && f < MAXF) {
        const int* r = faces + (long long)f * 3;
        g_faces4[f] = make_int4(__ldg(r + 0), __ldg(r + 1), __ldg(r + 2), 0);
    }
}

__global__ __launch_bounds__(256, 8)
void soft_normal_shader_kernel(
    const float* __restrict__ bary,    // (P,8,3)
    const float* __restrict__ dists,   // (P,8)
    const float* __restrict__ zbuf,    // (P,8)
    const int*   __restrict__ p2f,     // (P,8)
    float4*      __restrict__ out,     // (P,) rgba
    int npix)
{
    int pix = blockIdx.x * blockDim.x + threadIdx.x;
    if (pix >= npix) return;

    const long long base = (long long)pix * KSAMP;

    // ---- vectorized streaming loads ----
    float dk[KSAMP], zk[KSAMP];
    int fidx[KSAMP];
    {
        const float4* dp = reinterpret_cast<const float4*>(dists + base);
        const float4* zp = reinterpret_cast<const float4*>(zbuf  + base);
        const int4*   pp = reinterpret_cast<const int4*>(p2f + base);
        float4 d0 = __ldg(dp + 0), d1 = __ldg(dp + 1);
        float4 z0 = __ldg(zp + 0), z1 = __ldg(zp + 1);
        int4   a  = __ldg(pp + 0), b  = __ldg(pp + 1);
        dk[0]=d0.x; dk[1]=d0.y; dk[2]=d0.z; dk[3]=d0.w;
        dk[4]=d1.x; dk[5]=d1.y; dk[6]=d1.z; dk[7]=d1.w;
        zk[0]=z0.x; zk[1]=z0.y; zk[2]=z0.z; zk[3]=z0.w;
        zk[4]=z1.x; zk[5]=z1.y; zk[6]=z1.z; zk[7]=z1.w;
        fidx[0]=a.x; fidx[1]=a.y; fidx[2]=a.z; fidx[3]=a.w;
        fidx[4]=b.x; fidx[5]=b.y; fidx[6]=b.z; fidx[7]=b.w;
    }

    // ---- pass 1: alpha product, z_inv, z_inv_max ----
    float zi[KSAMP];
    float zmax = 0.0f;                 // zi >= 0 always (masked entries are 0)
    float one_minus_prod = 1.0f;
    #pragma unroll
    for (int k = 0; k < KSAMP; k++) {
        bool valid = fidx[k] >= 0;
        // sigmoid(-d/SIGMA) = 1/(1+exp(d/SIGMA))
        float p = valid ? (1.0f / (1.0f + __expf(dk[k] * SIGMA_INV))) : 0.0f;
        one_minus_prod *= (1.0f - p);
        zi[k] = valid ? (ZFAR_F - zk[k]) * INV_RANGE : 0.0f;
        zmax = fmaxf(zmax, zi[k]);
    }

    // ---- candidate mask: exp((zi-zmax)/GAMMA) flushes to 0 below ~-88 ----
    unsigned mask = 0;
    #pragma unroll
    for (int k = 0; k < KSAMP; k++) {
        if (fidx[k] >= 0 && (zi[k] - zmax) * GAMMA_INV > -88.0f)
            mask |= (1u << k);
    }

    // ---- compacted weight + gather loop (typically 1 iteration) ----
    float wsum = 0.0f;
    float accr = 0.0f, accg = 0.0f, accb = 0.0f;
    while (mask) {
        int k = __ffs(mask) - 1;
        mask &= mask - 1;
        float p = 1.0f / (1.0f + __expf(dk[k] * SIGMA_INV));
        float w = p * __expf((zi[k] - zmax) * GAMMA_INV);
        wsum += w;
        // lazy bary: load b0,b1; reconstruct b2 (barycentrics sum to ~1)
        const float* bp = bary + (base + k) * 3;
        float b0 = __ldg(bp + 0);
        float b1 = __ldg(bp + 1);
        float b2 = 1.0f - b0 - b1;
        // packed gathers: 1 int4 + 3 float4
        int4 fv = g_faces4[fidx[k]];
        float4 n0 = g_vn4[fv.x];
        float4 n1 = g_vn4[fv.y];
        float4 n2 = g_vn4[fv.z];
        float cr = b0 * n0.x + b1 * n1.x + b2 * n2.x;
        float cg = b0 * n0.y + b1 * n1.y + b2 * n2.y;
        float cb = b0 * n0.z + b1 * n1.z + b2 * n2.z;
        accr += w * cr;
        accg += w * cg;
        accb += w * cb;
    }

    // ---- blend ----
    float delta = fmaxf(__expf((EPS_F - zmax) * GAMMA_INV), EPS_F);
    float inv_denom = 1.0f / (wsum + delta);
    float4 o;
    o.x = (accr + delta) * inv_denom;   // background = (1,1,1)
    o.y = (accg + delta) * inv_denom;
    o.z = (accb + delta) * inv_denom;
    o.w = 1.0f - one_minus_prod;        // 1 - alpha
    out[pix] = o;
}

extern "C" void kernel_launch(void* const* d_in, const int* in_sizes, int n_in,
                              void* d_out, int out_size)
{
    const float* vn    = (const float*)d_in[0];
    const float* bary  = (const float*)d_in[1];
    const float* dists = (const float*)d_in[2];
    const float* zbuf  = (const float*)d_in[3];
    const int*   faces = (const int*)d_in[4];
    const int*   p2f   = (const int*)d_in[5];
    float4*      out   = (float4*)d_out;

    int V = in_sizes[0] / 3;
    int F = in_sizes[4] / 3;
    int npix = in_sizes[2] / KSAMP;   // N*H*W

    pack_vn_kernel<<<(V + 255) / 256, 256>>>(vn, V);
    pack_faces_kernel<<<(F + 255) / 256, 256>>>(faces, F);

    int threads = 256;
    int blocks = (npix + threads - 1) / threads;
    soft_normal_shader_kernel<<<blocks, threads>>>(bary, dists, zbuf, p2f, out, npix);
}

// round 5
// speedup vs baseline: 1.1416x; 1.1416x over previous
#include <cuda_runtime.h>
#include <cstdint>

// SoftNormalShader: gather vertex normals + barycentric interp + softmax RGB blend.
// N=4,H=512,W=512,K=8 ; V=50000, F=100000.
// Inputs (JAX x64 disabled => int arrays are int32):
//   0: verts_normals (V,3) f32   1: bary (P,8,3) f32   2: dists (P,8) f32
//   3: zbuf (P,8) f32            4: faces (F,3) i32    5: pix_to_face (P,8) i32
// Output: (N,H,W,4) float32
//
// R5: single prep kernel builds a per-FACE normal table (3 x float4 per face,
// L2-resident) removing the faces indirection from the hot path; main kernel
// does lazy bary + 3 wide gathers per passing sample (GAMMA=1e-4 underflow =>
// ~1.2 of 8 samples carry weight). Streaming hints keep one-pass data out of L2.

#define KSAMP 8
#define SIGMA_INV  1e4f
#define GAMMA_INV  1e4f
#define ZFAR_F     100.0f
#define INV_RANGE  (1.0f / 99.0f)
#define EPS_F      1e-10f

#define MAXF 131072

__device__ float4 g_fn[MAXF][3];   // per-face packed vertex normals

__global__ __launch_bounds__(256)
void prep_face_normals_kernel(const float* __restrict__ vn,
                              const int*   __restrict__ faces, int F)
{
    int f = blockIdx.x * blockDim.x + threadIdx.x;
    if (f >= F || f >= MAXF) return;
    const int* fr = faces + (long long)f * 3;
    int v0 = __ldg(fr + 0);
    int v1 = __ldg(fr + 1);
    int v2 = __ldg(fr + 2);
    const float* n0 = vn + (long long)v0 * 3;
    const float* n1 = vn + (long long)v1 * 3;
    const float* n2 = vn + (long long)v2 * 3;
    g_fn[f][0] = make_float4(__ldg(n0+0), __ldg(n0+1), __ldg(n0+2), 0.0f);
    g_fn[f][1] = make_float4(__ldg(n1+0), __ldg(n1+1), __ldg(n1+2), 0.0f);
    g_fn[f][2] = make_float4(__ldg(n2+0), __ldg(n2+1), __ldg(n2+2), 0.0f);
}

__global__ __launch_bounds__(256, 8)
void soft_normal_shader_kernel(
    const float* __restrict__ bary,    // (P,8,3)
    const float* __restrict__ dists,   // (P,8)
    const float* __restrict__ zbuf,    // (P,8)
    const int*   __restrict__ p2f,     // (P,8)
    float4*      __restrict__ out,     // (P,) rgba
    int npix)
{
    int pix = blockIdx.x * blockDim.x + threadIdx.x;
    if (pix >= npix) return;

    const long long base = (long long)pix * KSAMP;

    // ---- vectorized streaming loads (evict-first: one-pass data) ----
    float dk[KSAMP], zk[KSAMP];
    int fidx[KSAMP];
    {
        const float4* dp = reinterpret_cast<const float4*>(dists + base);
        const float4* zp = reinterpret_cast<const float4*>(zbuf  + base);
        const int4*   pp = reinterpret_cast<const int4*>(p2f + base);
        float4 d0 = __ldcs(dp + 0), d1 = __ldcs(dp + 1);
        float4 z0 = __ldcs(zp + 0), z1 = __ldcs(zp + 1);
        int4   a  = __ldcs(pp + 0), b  = __ldcs(pp + 1);
        dk[0]=d0.x; dk[1]=d0.y; dk[2]=d0.z; dk[3]=d0.w;
        dk[4]=d1.x; dk[5]=d1.y; dk[6]=d1.z; dk[7]=d1.w;
        zk[0]=z0.x; zk[1]=z0.y; zk[2]=z0.z; zk[3]=z0.w;
        zk[4]=z1.x; zk[5]=z1.y; zk[6]=z1.z; zk[7]=z1.w;
        fidx[0]=a.x; fidx[1]=a.y; fidx[2]=a.z; fidx[3]=a.w;
        fidx[4]=b.x; fidx[5]=b.y; fidx[6]=b.z; fidx[7]=b.w;
    }

    // ---- pass 1: alpha product, z_inv, z_inv_max ----
    float zi[KSAMP];
    float zmax = 0.0f;                 // zi >= 0 always (masked entries are 0)
    float one_minus_prod = 1.0f;
    #pragma unroll
    for (int k = 0; k < KSAMP; k++) {
        bool valid = fidx[k] >= 0;
        // sigmoid(-d/SIGMA) = 1/(1+exp(d/SIGMA))
        float p = valid ? (1.0f / (1.0f + __expf(dk[k] * SIGMA_INV))) : 0.0f;
        one_minus_prod *= (1.0f - p);
        zi[k] = valid ? (ZFAR_F - zk[k]) * INV_RANGE : 0.0f;
        zmax = fmaxf(zmax, zi[k]);
    }

    // ---- candidate mask: exp((zi-zmax)*1e4) flushes to 0 below ~-88 ----
    unsigned mask = 0;
    #pragma unroll
    for (int k = 0; k < KSAMP; k++) {
        if (fidx[k] >= 0 && (zi[k] - zmax) * GAMMA_INV > -88.0f)
            mask |= (1u << k);
    }

    // ---- compacted weight + gather loop (typically 1 iteration) ----
    float wsum = 0.0f;
    float accr = 0.0f, accg = 0.0f, accb = 0.0f;
    while (mask) {
        int k = __ffs(mask) - 1;
        mask &= mask - 1;
        float p = 1.0f / (1.0f + __expf(dk[k] * SIGMA_INV));
        float w = p * __expf((zi[k] - zmax) * GAMMA_INV);
        wsum += w;
        // lazy bary: b0,b1 loaded; b2 reconstructed (barycentrics sum to 1)
        const float* bp = bary + (base + k) * 3;
        float b0 = __ldg(bp + 0);
        float b1 = __ldg(bp + 1);
        float b2 = 1.0f - b0 - b1;
        // single-hop gather: per-face packed normals (L2-resident)
        const float4* fn = g_fn[fidx[k]];
        float4 n0 = __ldg(fn + 0);
        float4 n1 = __ldg(fn + 1);
        float4 n2 = __ldg(fn + 2);
        float cr = b0 * n0.x + b1 * n1.x + b2 * n2.x;
        float cg = b0 * n0.y + b1 * n1.y + b2 * n2.y;
        float cb = b0 * n0.z + b1 * n1.z + b2 * n2.z;
        accr += w * cr;
        accg += w * cg;
        accb += w * cb;
    }

    // ---- blend ----
    float delta = fmaxf(__expf((EPS_F - zmax) * GAMMA_INV), EPS_F);
    float inv_denom = 1.0f / (wsum + delta);
    float4 o;
    o.x = (accr + delta) * inv_denom;   // background = (1,1,1)
    o.y = (accg + delta) * inv_denom;
    o.z = (accb + delta) * inv_denom;
    o.w = 1.0f - one_minus_prod;        // 1 - alpha
    __stcs(out + pix, o);
}

extern "C" void kernel_launch(void* const* d_in, const int* in_sizes, int n_in,
                              void* d_out, int out_size)
{
    const float* vn    = (const float*)d_in[0];
    const float* bary  = (const float*)d_in[1];
    const float* dists = (const float*)d_in[2];
    const float* zbuf  = (const float*)d_in[3];
    const int*   faces = (const int*)d_in[4];
    const int*   p2f   = (const int*)d_in[5];
    float4*      out   = (float4*)d_out;

    int F = in_sizes[4] / 3;
    int npix = in_sizes[2] / KSAMP;   // N*H*W

    prep_face_normals_kernel<<<(F + 255) / 256, 256>>>(vn, faces, F);

    int threads = 256;
    int blocks = (npix + threads - 1) / threads;
    soft_normal_shader_kernel<<<blocks, threads>>>(bary, dists, zbuf, p2f, out, npix);
}

// round 6
// speedup vs baseline: 1.2255x; 1.0734x over previous
#include <cuda_runtime.h>
#include <cstdint>

// SoftNormalShader: gather vertex normals + barycentric interp + softmax RGB blend.
// N=4,H=512,W=512,K=8 ; V=50000, F=100000.
// Inputs (JAX x64 disabled => int arrays are int32):
//   0: verts_normals (V,3) f32   1: bary (P,8,3) f32   2: dists (P,8) f32
//   3: zbuf (P,8) f32            4: faces (F,3) i32    5: pix_to_face (P,8) i32
// Output: (N,H,W,4) float32
//
// R6: prep reshaped to one thread per (face,vertex) (3x parallelism, short
// chain); main kernel processes 2 pixels/thread with front-batched loads to
// double MLP. Per-face normal table (L2-resident) kills the double indirection;
// lazy bary + bitmask-compacted weight loop (GAMMA underflow => ~1.06 of 8
// samples carry weight).

#define KSAMP 8
#define SIGMA_INV  1e4f
#define GAMMA_INV  1e4f
#define ZFAR_F     100.0f
#define INV_RANGE  (1.0f / 99.0f)
#define EPS_F      1e-10f

#define MAXF 131072

__device__ float4 g_fn[MAXF][3];   // per-face packed vertex normals

__global__ __launch_bounds__(256)
void prep_face_normals_kernel(const float* __restrict__ vn,
                              const int*   __restrict__ faces, int F)
{
    int idx = blockIdx.x * blockDim.x + threadIdx.x;   // (face, vert) pairs
    int f = idx / 3;
    int j = idx - f * 3;
    if (f >= F || f >= MAXF) return;
    int v = __ldg(faces + (long long)f * 3 + j);
    const float* n = vn + (long long)v * 3;
    float x = __ldg(n + 0);
    float y = __ldg(n + 1);
    float z = __ldg(n + 2);
    g_fn[f][j] = make_float4(x, y, z, 0.0f);
}

#define PIX_PER_THREAD 2

__global__ __launch_bounds__(256, 4)
void soft_normal_shader_kernel(
    const float* __restrict__ bary,    // (P,8,3)
    const float* __restrict__ dists,   // (P,8)
    const float* __restrict__ zbuf,    // (P,8)
    const int*   __restrict__ p2f,     // (P,8)
    float4*      __restrict__ out,     // (P,) rgba
    int npix)
{
    int tid = blockIdx.x * blockDim.x + threadIdx.x;

    // two pixels, strided by total thread count so loads stay fully coalesced
    int nthreads = gridDim.x * blockDim.x;

    float dk[PIX_PER_THREAD][KSAMP], zk[PIX_PER_THREAD][KSAMP];
    int   fidx[PIX_PER_THREAD][KSAMP];
    int   pixv[PIX_PER_THREAD];

    // ---- front-batched streaming loads for both pixels (MLP=6x16B) ----
    #pragma unroll
    for (int j = 0; j < PIX_PER_THREAD; j++) {
        int pix = tid + j * nthreads;
        pixv[j] = pix;
        if (pix >= npix) { pixv[j] = -1; continue; }
        const long long base = (long long)pix * KSAMP;
        const float4* dp = reinterpret_cast<const float4*>(dists + base);
        const float4* zp = reinterpret_cast<const float4*>(zbuf  + base);
        const int4*   pp = reinterpret_cast<const int4*>(p2f + base);
        float4 d0 = __ldcs(dp + 0), d1 = __ldcs(dp + 1);
        float4 z0 = __ldcs(zp + 0), z1 = __ldcs(zp + 1);
        int4   a  = __ldcs(pp + 0), b  = __ldcs(pp + 1);
        dk[j][0]=d0.x; dk[j][1]=d0.y; dk[j][2]=d0.z; dk[j][3]=d0.w;
        dk[j][4]=d1.x; dk[j][5]=d1.y; dk[j][6]=d1.z; dk[j][7]=d1.w;
        zk[j][0]=z0.x; zk[j][1]=z0.y; zk[j][2]=z0.z; zk[j][3]=z0.w;
        zk[j][4]=z1.x; zk[j][5]=z1.y; zk[j][6]=z1.z; zk[j][7]=z1.w;
        fidx[j][0]=a.x; fidx[j][1]=a.y; fidx[j][2]=a.z; fidx[j][3]=a.w;
        fidx[j][4]=b.x; fidx[j][5]=b.y; fidx[j][6]=b.z; fidx[j][7]=b.w;
    }

    #pragma unroll
    for (int j = 0; j < PIX_PER_THREAD; j++) {
        if (pixv[j] < 0) continue;
        const long long base = (long long)pixv[j] * KSAMP;

        // ---- pass 1: alpha product, z_inv, z_inv_max ----
        float zi[KSAMP];
        float zmax = 0.0f;                 // zi >= 0 (masked entries are 0)
        float one_minus_prod = 1.0f;
        #pragma unroll
        for (int k = 0; k < KSAMP; k++) {
            bool valid = fidx[j][k] >= 0;
            float p = valid ? (1.0f / (1.0f + __expf(dk[j][k] * SIGMA_INV))) : 0.0f;
            one_minus_prod *= (1.0f - p);
            zi[k] = valid ? (ZFAR_F - zk[j][k]) * INV_RANGE : 0.0f;
            zmax = fmaxf(zmax, zi[k]);
        }

        // ---- candidate mask: exp((zi-zmax)*1e4) flushes to 0 below ~-88 ----
        unsigned mask = 0;
        #pragma unroll
        for (int k = 0; k < KSAMP; k++) {
            if (fidx[j][k] >= 0 && (zi[k] - zmax) * GAMMA_INV > -88.0f)
                mask |= (1u << k);
        }

        // ---- compacted weight + gather loop (typically 1 iteration) ----
        float wsum = 0.0f;
        float accr = 0.0f, accg = 0.0f, accb = 0.0f;
        while (mask) {
            int k = __ffs(mask) - 1;
            mask &= mask - 1;
            float p = 1.0f / (1.0f + __expf(dk[j][k] * SIGMA_INV));
            float w = p * __expf((zi[k] - zmax) * GAMMA_INV);
            wsum += w;
            // lazy bary: b0,b1 loaded; b2 reconstructed (sum == 1)
            const float* bp = bary + (base + k) * 3;
            float b0 = __ldg(bp + 0);
            float b1 = __ldg(bp + 1);
            float b2 = 1.0f - b0 - b1;
            // single-hop gather: per-face packed normals (L2-resident)
            const float4* fn = g_fn[fidx[j][k]];
            float4 n0 = __ldg(fn + 0);
            float4 n1 = __ldg(fn + 1);
            float4 n2 = __ldg(fn + 2);
            float cr = b0 * n0.x + b1 * n1.x + b2 * n2.x;
            float cg = b0 * n0.y + b1 * n1.y + b2 * n2.y;
            float cb = b0 * n0.z + b1 * n1.z + b2 * n2.z;
            accr += w * cr;
            accg += w * cg;
            accb += w * cb;
        }

        // ---- blend ----
        float delta = fmaxf(__expf((EPS_F - zmax) * GAMMA_INV), EPS_F);
        float inv_denom = 1.0f / (wsum + delta);
        float4 o;
        o.x = (accr + delta) * inv_denom;   // background = (1,1,1)
        o.y = (accg + delta) * inv_denom;
        o.z = (accb + delta) * inv_denom;
        o.w = 1.0f - one_minus_prod;        // 1 - alpha
        __stcs(out + pixv[j], o);
    }
}

extern "C" void kernel_launch(void* const* d_in, const int* in_sizes, int n_in,
                              void* d_out, int out_size)
{
    const float* vn    = (const float*)d_in[0];
    const float* bary  = (const float*)d_in[1];
    const float* dists = (const float*)d_in[2];
    const float* zbuf  = (const float*)d_in[3];
    const int*   faces = (const int*)d_in[4];
    const int*   p2f   = (const int*)d_in[5];
    float4*      out   = (float4*)d_out;

    int F = in_sizes[4] / 3;
    int npix = in_sizes[2] / KSAMP;   // N*H*W

    prep_face_normals_kernel<<<(3 * F + 255) / 256, 256>>>(vn, faces, F);

    int threads = 256;
    int total_threads = (npix + PIX_PER_THREAD - 1) / PIX_PER_THREAD;
    int blocks = (total_threads + threads - 1) / threads;
    soft_normal_shader_kernel<<<blocks, threads>>>(bary, dists, zbuf, p2f, out, npix);
}

// round 7
// speedup vs baseline: 1.2722x; 1.0381x over previous
#include <cuda_runtime.h>
#include <cstdint>

// SoftNormalShader: gather vertex normals + barycentric interp + softmax RGB blend.
// N=4,H=512,W=512,K=8 ; V=50000, F=100000.
// Inputs (JAX x64 disabled => int arrays are int32):
//   0: verts_normals (V,3) f32   1: bary (P,8,3) f32   2: dists (P,8) f32
//   3: zbuf (P,8) f32            4: faces (F,3) i32    5: pix_to_face (P,8) i32
// Output: (N,H,W,4) float32
//
// R7: 2 px/thread front-batched loads (MLP) + register cap (256,5) to restore
// occupancy (R6 lost half the warps to regs=56). pm cached from pass 1 so the
// gather loop skips the sigmoid recompute. Per-face normal table (L2-resident)
// built by a short prep kernel; lazy bary; bitmask-compacted weight loop
// (GAMMA=1e-4 underflow => ~1.06 of 8 samples carry weight).

#define KSAMP 8
#define SIGMA_INV  1e4f
#define GAMMA_INV  1e4f
#define ZFAR_F     100.0f
#define INV_RANGE  (1.0f / 99.0f)
#define EPS_F      1e-10f

#define MAXF 131072

__device__ float4 g_fn[MAXF][3];   // per-face packed vertex normals

__global__ __launch_bounds__(256)
void prep_face_normals_kernel(const float* __restrict__ vn,
                              const int*   __restrict__ faces, int F)
{
    int idx = blockIdx.x * blockDim.x + threadIdx.x;   // (face, vert) pairs
    int f = idx / 3;
    int j = idx - f * 3;
    if (f >= F || f >= MAXF) return;
    int v = __ldg(faces + (long long)f * 3 + j);
    const float* n = vn + (long long)v * 3;
    float x = __ldg(n + 0);
    float y = __ldg(n + 1);
    float z = __ldg(n + 2);
    g_fn[f][j] = make_float4(x, y, z, 0.0f);
}

#define PIX_PER_THREAD 2

__global__ __launch_bounds__(256, 5)
void soft_normal_shader_kernel(
    const float* __restrict__ bary,    // (P,8,3)
    const float* __restrict__ dists,   // (P,8)
    const float* __restrict__ zbuf,    // (P,8)
    const int*   __restrict__ p2f,     // (P,8)
    float4*      __restrict__ out,     // (P,) rgba
    int npix)
{
    int tid = blockIdx.x * blockDim.x + threadIdx.x;
    int nthreads = gridDim.x * blockDim.x;

    float4 dv[PIX_PER_THREAD][2], zv[PIX_PER_THREAD][2];
    int4   pv[PIX_PER_THREAD][2];

    // ---- front-batched streaming loads for both pixels (12 x 16B in flight) ----
    #pragma unroll
    for (int j = 0; j < PIX_PER_THREAD; j++) {
        int pix = tid + j * nthreads;
        if (pix >= npix) pix = npix - 1;           // clamped duplicate (grid sized exactly anyway)
        const long long base = (long long)pix * KSAMP;
        const float4* dp = reinterpret_cast<const float4*>(dists + base);
        const float4* zp = reinterpret_cast<const float4*>(zbuf  + base);
        const int4*   pp = reinterpret_cast<const int4*>(p2f + base);
        dv[j][0] = __ldcs(dp + 0); dv[j][1] = __ldcs(dp + 1);
        zv[j][0] = __ldcs(zp + 0); zv[j][1] = __ldcs(zp + 1);
        pv[j][0] = __ldcs(pp + 0); pv[j][1] = __ldcs(pp + 1);
    }

    #pragma unroll
    for (int j = 0; j < PIX_PER_THREAD; j++) {
        int pix = tid + j * nthreads;
        if (pix >= npix) continue;
        const long long base = (long long)pix * KSAMP;

        const float* df = reinterpret_cast<const float*>(&dv[j][0]);
        const float* zf = reinterpret_cast<const float*>(&zv[j][0]);
        const int*   pf = reinterpret_cast<const int*>(&pv[j][0]);

        // ---- pass 1: sigmoid probs, z_inv, z_inv_max, alpha product ----
        float pm[KSAMP], zi[KSAMP];
        float zmax = 0.0f;                 // zi >= 0 (masked entries are 0)
        float one_minus_prod = 1.0f;
        #pragma unroll
        for (int k = 0; k < KSAMP; k++) {
            bool valid = pf[k] >= 0;
            float p = valid ? (1.0f / (1.0f + __expf(df[k] * SIGMA_INV))) : 0.0f;
            pm[k] = p;
            one_minus_prod *= (1.0f - p);
            zi[k] = valid ? (ZFAR_F - zf[k]) * INV_RANGE : 0.0f;
            zmax = fmaxf(zmax, zi[k]);
        }

        // ---- candidate mask: exp((zi-zmax)*1e4) flushes to 0 below ~-88 ----
        unsigned mask = 0;
        #pragma unroll
        for (int k = 0; k < KSAMP; k++) {
            if (pf[k] >= 0 && (zi[k] - zmax) * GAMMA_INV > -88.0f)
                mask |= (1u << k);
        }

        // ---- compacted weight + gather loop (typically 1 iteration) ----
        float wsum = 0.0f;
        float accr = 0.0f, accg = 0.0f, accb = 0.0f;
        while (mask) {
            int k = __ffs(mask) - 1;
            mask &= mask - 1;
            float w = pm[k] * __expf((zi[k] - zmax) * GAMMA_INV);
            wsum += w;
            // lazy bary: b0,b1 loaded; b2 reconstructed (sum == 1)
            const float* bp = bary + (base + k) * 3;
            float b0 = __ldg(bp + 0);
            float b1 = __ldg(bp + 1);
            float b2 = 1.0f - b0 - b1;
            // single-hop gather: per-face packed normals (L2-resident)
            const float4* fn = g_fn[pf[k]];
            float4 n0 = __ldg(fn + 0);
            float4 n1 = __ldg(fn + 1);
            float4 n2 = __ldg(fn + 2);
            accr += w * (b0 * n0.x + b1 * n1.x + b2 * n2.x);
            accg += w * (b0 * n0.y + b1 * n1.y + b2 * n2.y);
            accb += w * (b0 * n0.z + b1 * n1.z + b2 * n2.z);
        }

        // ---- blend ----
        float delta = fmaxf(__expf((EPS_F - zmax) * GAMMA_INV), EPS_F);
        float inv_denom = 1.0f / (wsum + delta);
        float4 o;
        o.x = (accr + delta) * inv_denom;   // background = (1,1,1)
        o.y = (accg + delta) * inv_denom;
        o.z = (accb + delta) * inv_denom;
        o.w = 1.0f - one_minus_prod;        // 1 - alpha
        __stcs(out + pix, o);
    }
}

extern "C" void kernel_launch(void* const* d_in, const int* in_sizes, int n_in,
                              void* d_out, int out_size)
{
    const float* vn    = (const float*)d_in[0];
    const float* bary  = (const float*)d_in[1];
    const float* dists = (const float*)d_in[2];
    const float* zbuf  = (const float*)d_in[3];
    const int*   faces = (const int*)d_in[4];
    const int*   p2f   = (const int*)d_in[5];
    float4*      out   = (float4*)d_out;

    int F = in_sizes[4] / 3;
    int npix = in_sizes[2] / KSAMP;   // N*H*W

    prep_face_normals_kernel<<<(3 * F + 255) / 256, 256>>>(vn, faces, F);

    int threads = 256;
    int total_threads = (npix + PIX_PER_THREAD - 1) / PIX_PER_THREAD;
    int blocks = (total_threads + threads - 1) / threads;
    soft_normal_shader_kernel<<<blocks, threads>>>(bary, dists, zbuf, p2f, out, npix);
}